// round 2
// baseline (speedup 1.0000x reference)
#include <cuda_runtime.h>
#include <math_constants.h>

#define N_NODES 50000
#define N_EDGES 800000
#define C_IN   64
#define C_OUT  64
#define KPRE   67    // feat(64) + src pos(3) -> precomputable part of C_MSG
#define C_MSG  71
#define NUM_TYPES 2

// Scratch (device globals — no runtime allocation allowed)
__device__ float    g_z[(size_t)N_NODES * NUM_TYPES * C_OUT];  // 25.6 MB
__device__ int      g_cnt[N_NODES];
__device__ int      g_off[N_NODES + 1];
__device__ int      g_pos[N_NODES];
__device__ unsigned g_rec[N_EDGES];

// ---------- Phase A: z[n,t,c] = sum_{k<67} x[n,k] * W[t,k,c] + b[t,c] ----------
__global__ void precompute_kernel(const float* __restrict__ feat,
                                  const float* __restrict__ pos,
                                  const float* __restrict__ W,
                                  const float* __restrict__ b,
                                  int n_nodes) {
    __shared__ float W_sh[NUM_TYPES][KPRE][C_OUT];   // 34.3 KB
    __shared__ float b_sh[NUM_TYPES][C_OUT];
    __shared__ float x_sh[4][KPRE];

    for (int i = threadIdx.x; i < NUM_TYPES * KPRE * C_OUT; i += blockDim.x) {
        int t = i / (KPRE * C_OUT);
        int r = i % (KPRE * C_OUT);
        int k = r / C_OUT, c = r % C_OUT;
        W_sh[t][k][c] = W[(t * C_MSG + k) * C_OUT + c];
    }
    for (int i = threadIdx.x; i < NUM_TYPES * C_OUT; i += blockDim.x)
        b_sh[i / C_OUT][i % C_OUT] = b[i];
    __syncthreads();

    const int tid = threadIdx.x;
    const int t = (tid >> 6) & 1;
    const int c = tid & 63;
    const int l = tid >> 7;   // 0 or 1

    const int ngroups = (n_nodes + 3) >> 2;
    for (int g = blockIdx.x; g < ngroups; g += gridDim.x) {
        const int base = g * 4;
        __syncthreads();
        for (int i = tid; i < 4 * KPRE; i += blockDim.x) {
            int nl = i / KPRE, k = i % KPRE;
            int n = base + nl;
            float v = 0.f;
            if (n < n_nodes)
                v = (k < C_IN) ? feat[(size_t)n * C_IN + k]
                               : pos[(size_t)n * 3 + (k - C_IN)];
            x_sh[nl][k] = v;
        }
        __syncthreads();

        float acc0 = b_sh[t][c];
        float acc1 = acc0;
        #pragma unroll
        for (int k = 0; k < KPRE; k++) {
            float w = W_sh[t][k][c];
            acc0 = fmaf(x_sh[l][k],     w, acc0);
            acc1 = fmaf(x_sh[l + 2][k], w, acc1);
        }
        int n0 = base + l, n1 = base + l + 2;
        if (n0 < n_nodes) g_z[((size_t)n0 * NUM_TYPES + t) * C_OUT + c] = acc0;
        if (n1 < n_nodes) g_z[((size_t)n1 * NUM_TYPES + t) * C_OUT + c] = acc1;
    }
}

// ---------- CSR build ----------
__global__ void zero_cnt_kernel(int n_nodes) {
    int i = blockIdx.x * blockDim.x + threadIdx.x;
    if (i < n_nodes) g_cnt[i] = 0;
}

__global__ void hist_kernel(const int* __restrict__ dst, int n_edges) {
    int e = blockIdx.x * blockDim.x + threadIdx.x;
    if (e < n_edges) atomicAdd(&g_cnt[dst[e]], 1);
}

// single-block exclusive scan over g_cnt -> g_off (and g_pos copy)
__global__ void scan_kernel(int n_nodes) {
    __shared__ int part[1024];
    const int tid = threadIdx.x;
    const int per = (n_nodes + 1023) / 1024;
    const int base = tid * per;

    int s = 0;
    for (int i = 0; i < per; i++) {
        int idx = base + i;
        if (idx < n_nodes) s += g_cnt[idx];
    }
    part[tid] = s;
    __syncthreads();
    for (int d = 1; d < 1024; d <<= 1) {
        int add = (tid >= d) ? part[tid - d] : 0;
        __syncthreads();
        part[tid] += add;
        __syncthreads();
    }
    int run = (tid == 0) ? 0 : part[tid - 1];
    for (int i = 0; i < per; i++) {
        int idx = base + i;
        if (idx < n_nodes) {
            g_off[idx] = run;
            g_pos[idx] = run;
            run += g_cnt[idx];
        }
    }
    if (tid == 0) g_off[n_nodes] = part[1023];
}

// scatter packed (src | attr<<17) records into dst-sorted buckets
__global__ void scatter_kernel(const int* __restrict__ src,
                               const int* __restrict__ dst,
                               const int* __restrict__ attr,
                               int n_edges) {
    int e = blockIdx.x * blockDim.x + threadIdx.x;
    if (e >= n_edges) return;
    int d = dst[e];
    int p = atomicAdd(&g_pos[d], 1);
    g_rec[p] = (unsigned)src[e] | ((unsigned)attr[e] << 17);
}

// ---------- per-destination reduce: one warp per node, max in registers ----------
__global__ void reduce_kernel(const float* __restrict__ pos,
                              const float* __restrict__ W,
                              float* __restrict__ out,
                              int n_nodes) {
    __shared__ float wp[NUM_TYPES * 4 * C_OUT];   // W rows 67..70 per type (2 KB)
    for (int i = threadIdx.x; i < NUM_TYPES * 4 * C_OUT; i += blockDim.x) {
        int t = i / (4 * C_OUT);
        int r = i % (4 * C_OUT);
        int k = KPRE + r / C_OUT, c = r % C_OUT;
        wp[i] = W[(t * C_MSG + k) * C_OUT + c];
    }
    __syncthreads();

    const int lane = threadIdx.x & 31;
    const int node = (blockIdx.x * blockDim.x + threadIdx.x) >> 5;
    if (node >= n_nodes) return;

    const int beg = g_off[node];
    const int len = g_off[node + 1] - beg;

    float m0 = -CUDART_INF_F, m1 = -CUDART_INF_F;

    if (len > 0) {
        const float px = pos[3 * node], py = pos[3 * node + 1], pz = pos[3 * node + 2];

        // software pipeline: stage loads for edge i while computing edge i-1
        unsigned rnext = (len > 1) ? g_rec[beg + 1] : 0u;
        unsigned rcur  = g_rec[beg];
        int   si = rcur & 0x1FFFF;
        int   tc = (int)(rcur >> 17);
        float sx = pos[3 * si], sy = pos[3 * si + 1], sz = pos[3 * si + 2];
        const float* zr = g_z + ((size_t)si * NUM_TYPES + tc) * C_OUT;
        float z0 = zr[lane], z1 = zr[lane + 32];

        for (int i = 0; i < len; i++) {
            // issue loads for i+1
            int tn = 0;
            float sxn = 0.f, syn = 0.f, szn = 0.f, z0n = 0.f, z1n = 0.f;
            unsigned rnn = 0u;
            if (i + 1 < len) {
                int sin = rnext & 0x1FFFF;
                tn = (int)(rnext >> 17);
                sxn = pos[3 * sin]; syn = pos[3 * sin + 1]; szn = pos[3 * sin + 2];
                const float* zrn = g_z + ((size_t)sin * NUM_TYPES + tn) * C_OUT;
                z0n = zrn[lane]; z1n = zrn[lane + 32];
            }
            if (i + 2 < len) rnn = g_rec[beg + i + 2];

            // compute edge i
            float dx = px - sx, dy = py - sy, dz = pz - sz;
            float dist = sqrtf(fmaf(dx, dx, fmaf(dy, dy, dz * dz)));
            const float* w0 = wp + tc * 4 * C_OUT;

            float y0 = z0;
            y0 = fmaf(dx,   w0[lane],             y0);
            y0 = fmaf(dy,   w0[C_OUT + lane],     y0);
            y0 = fmaf(dz,   w0[2 * C_OUT + lane], y0);
            y0 = fmaf(dist, w0[3 * C_OUT + lane], y0);

            float y1 = z1;
            y1 = fmaf(dx,   w0[lane + 32],             y1);
            y1 = fmaf(dy,   w0[C_OUT + lane + 32],     y1);
            y1 = fmaf(dz,   w0[2 * C_OUT + lane + 32], y1);
            y1 = fmaf(dist, w0[3 * C_OUT + lane + 32], y1);

            m0 = fmaxf(m0, y0);
            m1 = fmaxf(m1, y1);

            // rotate pipeline
            sx = sxn; sy = syn; sz = szn; z0 = z0n; z1 = z1n; tc = tn; rnext = rnn;
        }
    } else {
        m0 = 0.f;   // empty segment -> 0 (matches isfinite fixup)
        m1 = 0.f;
    }

    out[(size_t)node * C_OUT + lane]      = m0;
    out[(size_t)node * C_OUT + lane + 32] = m1;
}

extern "C" void kernel_launch(void* const* d_in, const int* in_sizes, int n_in,
                              void* d_out, int out_size) {
    const float* feat = (const float*)d_in[0];
    const float* pos  = (const float*)d_in[1];
    const float* W    = (const float*)d_in[2];
    const float* b    = (const float*)d_in[3];
    const int* ei     = (const int*)d_in[4];
    const int* attr   = (const int*)d_in[5];

    int n_nodes = in_sizes[0] / C_IN;
    int n_edges = in_sizes[5];
    float* out = (float*)d_out;

    const int* src = ei;
    const int* dst = ei + n_edges;

    precompute_kernel<<<1184, 256>>>(feat, pos, W, b, n_nodes);
    zero_cnt_kernel<<<(n_nodes + 255) / 256, 256>>>(n_nodes);
    hist_kernel<<<(n_edges + 255) / 256, 256>>>(dst, n_edges);
    scan_kernel<<<1, 1024>>>(n_nodes);
    scatter_kernel<<<(n_edges + 255) / 256, 256>>>(src, dst, attr, n_edges);
    reduce_kernel<<<(n_nodes * 32 + 255) / 256, 256>>>(pos, W, out, n_nodes);
}

// round 3
// speedup vs baseline: 1.7373x; 1.7373x over previous
#include <cuda_runtime.h>
#include <math_constants.h>

#define N_NODES 50000
#define N_EDGES 800000
#define C_IN   64
#define C_OUT  64
#define KPRE   67    // feat(64) + src pos(3) -> precomputable part of C_MSG
#define C_MSG  71
#define NUM_TYPES 2
#define SCAN_BLK 256

// Scratch (device globals — no runtime allocation allowed)
__device__ float    g_z[(size_t)N_NODES * NUM_TYPES * C_OUT];  // 25.6 MB
__device__ int      g_cnt[N_NODES];
__device__ int      g_off[N_NODES + 1];
__device__ int      g_pos[N_NODES];
__device__ unsigned g_rec[N_EDGES];
__device__ int      g_bsum[SCAN_BLK];
__device__ int      g_bpre[SCAN_BLK];
__device__ int      g_total;

// ---------- Phase A: z[n,t,c] = sum_{k<67} x[n,k] * W[t,k,c] + b[t,c] ----------
// Each thread owns fixed (t, c): W column lives in 67 registers, loaded once.
// 4 nodes per thread, 8 nodes per block iteration. x broadcast from smem.
__global__ void __launch_bounds__(256) precompute_kernel(
        const float* __restrict__ feat,
        const float* __restrict__ pos,
        const float* __restrict__ W,
        const float* __restrict__ b,
        int n_nodes) {
    __shared__ float x_sh[8][KPRE];

    const int tid = threadIdx.x;
    const int c = tid & 63;
    const int l = (tid >> 6) & 1;   // node-slot group: 0 -> nodes 0..3, 1 -> 4..7
    const int t = tid >> 7;

    float Wreg[KPRE];
    #pragma unroll
    for (int k = 0; k < KPRE; k++)
        Wreg[k] = W[(t * C_MSG + k) * C_OUT + c];
    const float bias = b[t * C_OUT + c];

    const int ngroups = (n_nodes + 7) >> 3;
    for (int g = blockIdx.x; g < ngroups; g += gridDim.x) {
        const int base = g * 8;
        __syncthreads();
        for (int i = tid; i < 8 * KPRE; i += 256) {
            int nl = i / KPRE, k = i - nl * KPRE;
            int n = base + nl;
            float v = 0.f;
            if (n < n_nodes)
                v = (k < C_IN) ? feat[(size_t)n * C_IN + k]
                               : pos[(size_t)n * 3 + (k - C_IN)];
            x_sh[nl][k] = v;
        }
        __syncthreads();

        float acc0 = bias, acc1 = bias, acc2 = bias, acc3 = bias;
        #pragma unroll
        for (int k = 0; k < KPRE; k++) {
            float w = Wreg[k];
            acc0 = fmaf(x_sh[l * 4 + 0][k], w, acc0);
            acc1 = fmaf(x_sh[l * 4 + 1][k], w, acc1);
            acc2 = fmaf(x_sh[l * 4 + 2][k], w, acc2);
            acc3 = fmaf(x_sh[l * 4 + 3][k], w, acc3);
        }
        int n0 = base + l * 4;
        if (n0 + 0 < n_nodes) g_z[((size_t)(n0 + 0) * NUM_TYPES + t) * C_OUT + c] = acc0;
        if (n0 + 1 < n_nodes) g_z[((size_t)(n0 + 1) * NUM_TYPES + t) * C_OUT + c] = acc1;
        if (n0 + 2 < n_nodes) g_z[((size_t)(n0 + 2) * NUM_TYPES + t) * C_OUT + c] = acc2;
        if (n0 + 3 < n_nodes) g_z[((size_t)(n0 + 3) * NUM_TYPES + t) * C_OUT + c] = acc3;
    }
}

// ---------- CSR build ----------
__global__ void zero_cnt_kernel(int n_nodes) {
    int i = blockIdx.x * blockDim.x + threadIdx.x;
    if (i < n_nodes) g_cnt[i] = 0;
}

__global__ void hist_kernel(const int* __restrict__ dst, int n_edges) {
    int e = blockIdx.x * blockDim.x + threadIdx.x;
    if (e < n_edges) atomicAdd(&g_cnt[dst[e]], 1);
}

// Level 1: per-block (256-wide) local exclusive scan; block sums to g_bsum.
__global__ void scan1_kernel(int n_nodes) {
    __shared__ int sm[SCAN_BLK];
    const int tid = threadIdx.x;
    const int gid = blockIdx.x * SCAN_BLK + tid;
    int v = (gid < n_nodes) ? g_cnt[gid] : 0;
    sm[tid] = v;
    __syncthreads();
    #pragma unroll
    for (int d = 1; d < SCAN_BLK; d <<= 1) {
        int a = (tid >= d) ? sm[tid - d] : 0;
        __syncthreads();
        sm[tid] += a;
        __syncthreads();
    }
    int incl = sm[tid];
    if (gid < n_nodes) g_off[gid] = incl - v;   // local exclusive
    if (tid == SCAN_BLK - 1) g_bsum[blockIdx.x] = incl;
}

// Level 2: single block scans the (<=256) block sums.
__global__ void scan2_kernel(int nblocks) {
    __shared__ int sm[SCAN_BLK];
    const int tid = threadIdx.x;
    int v = (tid < nblocks) ? g_bsum[tid] : 0;
    sm[tid] = v;
    __syncthreads();
    #pragma unroll
    for (int d = 1; d < SCAN_BLK; d <<= 1) {
        int a = (tid >= d) ? sm[tid - d] : 0;
        __syncthreads();
        sm[tid] += a;
        __syncthreads();
    }
    int incl = sm[tid];
    if (tid < nblocks) g_bpre[tid] = incl - v;  // exclusive
    if (tid == nblocks - 1) g_total = incl;
}

// Level 3: add block prefixes; also init g_pos and write total.
__global__ void scan3_kernel(int n_nodes) {
    int i = blockIdx.x * blockDim.x + threadIdx.x;
    if (i < n_nodes) {
        int v = g_off[i] + g_bpre[i >> 8];
        g_off[i] = v;
        g_pos[i] = v;
    }
    if (i == 0) g_off[n_nodes] = g_total;
}

// scatter packed (src | attr<<17) records into dst-sorted buckets
__global__ void scatter_kernel(const int* __restrict__ src,
                               const int* __restrict__ dst,
                               const int* __restrict__ attr,
                               int n_edges) {
    int e = blockIdx.x * blockDim.x + threadIdx.x;
    if (e >= n_edges) return;
    int d = dst[e];
    int p = atomicAdd(&g_pos[d], 1);
    g_rec[p] = (unsigned)src[e] | ((unsigned)attr[e] << 17);
}

// ---------- per-destination reduce: one warp per node, 2-deep SW pipeline ----------
#define FILL(S, IDX)                                                    \
    do {                                                                \
        unsigned r = g_rec[beg + (IDX)];                                \
        int si = r & 0x1FFFF;                                           \
        t##S = (int)(r >> 17);                                          \
        sx##S = pos[3 * si];                                            \
        sy##S = pos[3 * si + 1];                                        \
        sz##S = pos[3 * si + 2];                                        \
        const float* zr = g_z + ((size_t)si * NUM_TYPES + t##S) * C_OUT;\
        z0##S = zr[lane];                                               \
        z1##S = zr[lane + 32];                                          \
    } while (0)

#define COMPUTE(S)                                                      \
    do {                                                                \
        float dx = px - sx##S, dy = py - sy##S, dz = pz - sz##S;        \
        float dist = sqrtf(fmaf(dx, dx, fmaf(dy, dy, dz * dz)));        \
        const float* w0 = wp + t##S * 4 * C_OUT;                        \
        float y0 = z0##S;                                               \
        y0 = fmaf(dx,   w0[lane],             y0);                      \
        y0 = fmaf(dy,   w0[C_OUT + lane],     y0);                      \
        y0 = fmaf(dz,   w0[2 * C_OUT + lane], y0);                      \
        y0 = fmaf(dist, w0[3 * C_OUT + lane], y0);                      \
        float y1 = z1##S;                                               \
        y1 = fmaf(dx,   w0[lane + 32],             y1);                 \
        y1 = fmaf(dy,   w0[C_OUT + lane + 32],     y1);                 \
        y1 = fmaf(dz,   w0[2 * C_OUT + lane + 32], y1);                 \
        y1 = fmaf(dist, w0[3 * C_OUT + lane + 32], y1);                 \
        m0 = fmaxf(m0, y0);                                             \
        m1 = fmaxf(m1, y1);                                             \
    } while (0)

__global__ void __launch_bounds__(256) reduce_kernel(
        const float* __restrict__ pos,
        const float* __restrict__ W,
        float* __restrict__ out,
        int n_nodes) {
    __shared__ float wp[NUM_TYPES * 4 * C_OUT];   // W rows 67..70 per type (2 KB)
    for (int i = threadIdx.x; i < NUM_TYPES * 4 * C_OUT; i += blockDim.x) {
        int t = i / (4 * C_OUT);
        int r = i % (4 * C_OUT);
        int k = KPRE + r / C_OUT, c = r % C_OUT;
        wp[i] = W[(t * C_MSG + k) * C_OUT + c];
    }
    __syncthreads();

    const int lane = threadIdx.x & 31;
    const int node = (blockIdx.x * blockDim.x + threadIdx.x) >> 5;
    if (node >= n_nodes) return;

    const int beg = g_off[node];
    const int len = g_off[node + 1] - beg;

    float m0 = 0.f, m1 = 0.f;   // empty segment -> 0
    if (len > 0) {
        m0 = -CUDART_INF_F; m1 = -CUDART_INF_F;
        const float px = pos[3 * node], py = pos[3 * node + 1], pz = pos[3 * node + 2];

        float sxA, syA, szA, z0A, z1A; int tA;
        float sxB, syB, szB, z0B, z1B; int tB;

        FILL(A, 0);
        if (len > 1) FILL(B, 1);

        int i = 0;
        while (true) {
            COMPUTE(A);
            if (i + 2 < len) FILL(A, i + 2);
            if (++i >= len) break;
            COMPUTE(B);
            if (i + 2 < len) FILL(B, i + 2);
            if (++i >= len) break;
        }
    }

    out[(size_t)node * C_OUT + lane]      = m0;
    out[(size_t)node * C_OUT + lane + 32] = m1;
}

extern "C" void kernel_launch(void* const* d_in, const int* in_sizes, int n_in,
                              void* d_out, int out_size) {
    const float* feat = (const float*)d_in[0];
    const float* pos  = (const float*)d_in[1];
    const float* W    = (const float*)d_in[2];
    const float* b    = (const float*)d_in[3];
    const int* ei     = (const int*)d_in[4];
    const int* attr   = (const int*)d_in[5];

    int n_nodes = in_sizes[0] / C_IN;
    int n_edges = in_sizes[5];
    float* out = (float*)d_out;

    const int* src = ei;
    const int* dst = ei + n_edges;

    int scan_blocks = (n_nodes + SCAN_BLK - 1) / SCAN_BLK;   // 196 <= 256

    precompute_kernel<<<1184, 256>>>(feat, pos, W, b, n_nodes);
    zero_cnt_kernel<<<(n_nodes + 255) / 256, 256>>>(n_nodes);
    hist_kernel<<<(n_edges + 255) / 256, 256>>>(dst, n_edges);
    scan1_kernel<<<scan_blocks, SCAN_BLK>>>(n_nodes);
    scan2_kernel<<<1, SCAN_BLK>>>(scan_blocks);
    scan3_kernel<<<(n_nodes + 255) / 256, 256>>>(n_nodes);
    scatter_kernel<<<(n_edges + 255) / 256, 256>>>(src, dst, attr, n_edges);
    reduce_kernel<<<(n_nodes * 32 + 255) / 256, 256>>>(pos, W, out, n_nodes);
}